// round 12
// baseline (speedup 1.0000x reference)
#include <cuda_runtime.h>
#include <cuda_fp16.h>
#include <cstdint>

#define LB 2
#define LR 64
#define LL 512
#define LH 1024
#define LAH 512

__device__ __half g_wq[LAH * LH], g_wk[LAH * LH], g_wv[LAH * LH];
__device__ __half g_q[(size_t)LB * LL * LAH];
__device__ __half g_k[(size_t)LB * LL * LAH];
__device__ float  g_s[(size_t)LB * 8 * LL * LL];
__device__ __half g_probs[(size_t)LB * 8 * LL * LL];
__device__ __half g_v[(size_t)LB * LR * LL * LAH];

// ---------------------------------------------------------------------------
__device__ __forceinline__ void ldsm4(uint32_t r[4], uint32_t a) {
    asm volatile("ldmatrix.sync.aligned.m8n8.x4.shared.b16 {%0,%1,%2,%3}, [%4];"
                 : "=r"(r[0]), "=r"(r[1]), "=r"(r[2]), "=r"(r[3]) : "r"(a));
}
__device__ __forceinline__ void ldsm4t(uint32_t r[4], uint32_t a) {
    asm volatile("ldmatrix.sync.aligned.m8n8.x4.trans.shared.b16 {%0,%1,%2,%3}, [%4];"
                 : "=r"(r[0]), "=r"(r[1]), "=r"(r[2]), "=r"(r[3]) : "r"(a));
}
__device__ __forceinline__ void mma16816(float c[4], const uint32_t a[4], const uint32_t b[2]) {
    asm volatile(
        "mma.sync.aligned.m16n8k16.row.col.f32.f16.f16.f32 "
        "{%0,%1,%2,%3}, {%4,%5,%6,%7}, {%8,%9}, {%0,%1,%2,%3};"
        : "+f"(c[0]), "+f"(c[1]), "+f"(c[2]), "+f"(c[3])
        : "r"(a[0]), "r"(a[1]), "r"(a[2]), "r"(a[3]), "r"(b[0]), "r"(b[1]));
}
__device__ __forceinline__ uint32_t pk2(float x, float y) {
    __half2 h = __floats2half2_rn(x, y);
    return *(uint32_t*)&h;
}
__device__ __forceinline__ uint4 cvt8(float4 a, float4 b) {
    uint4 u;
    u.x = pk2(a.x, a.y); u.y = pk2(a.z, a.w);
    u.z = pk2(b.x, b.y); u.w = pk2(b.z, b.w);
    return u;
}
// [rows][32-half] rows of 4x16B chunks, swizzle c ^ ((row>>1)&3)
__device__ __forceinline__ uint32_t swA(int row, int c) {
    return (uint32_t)((row * 4 + (c ^ ((row >> 1) & 3))) * 16);
}
// [rows][64-half] rows of 8x16B chunks (128B rows), SW128: c ^ (row&7)
__device__ __forceinline__ uint32_t swB8(int row, int c) {
    return (uint32_t)((row * 8 + (c ^ (row & 7))) * 16);
}
__device__ __forceinline__ void cpa16(uint32_t dst, const void* src) {
    asm volatile("cp.async.cg.shared.global [%0], [%1], 16;" :: "r"(dst), "l"(src));
}
__device__ __forceinline__ void cpa_commit() {
    asm volatile("cp.async.commit_group;" ::: "memory");
}
template<int N>
__device__ __forceinline__ void cpa_wait() {
    asm volatile("cp.async.wait_group %0;" :: "n"(N) : "memory");
}

// ---------------------------------------------------------------------------
// single weight fp32 -> half: grid 256
// ---------------------------------------------------------------------------
__global__ void f2h_kernel(const float* __restrict__ s, __half* __restrict__ d)
{
    const long j = ((long)blockIdx.x * 256 + threadIdx.x) * 8;
    float4 x = *(const float4*)(s + j);
    float4 y = *(const float4*)(s + j + 4);
    *(uint4*)(d + j) = cvt8(x, y);
}

// ---------------------------------------------------------------------------
// V projection v2: C = hidden @ Wv^T + bv (half out)
// BM=64, BN=256, BK=64. 8 warps (2m x 4n), warp 32x64, acc 64 regs.
// 2-stage pipeline (A 8KB + B 32KB = 40KB/stage, 80KB total) -> 2 CTAs/SM.
// grid (mblocks, 2): A read twice (one per n-block), W L2-resident.
// ---------------------------------------------------------------------------
__global__ __launch_bounds__(256, 2)
void v_proj(const float* __restrict__ A, const __half* __restrict__ W,
            const float* __restrict__ bias, __half* __restrict__ C, int blk0)
{
    extern __shared__ __align__(16) unsigned char sm[];
    const uint32_t smBase = (uint32_t)__cvta_generic_to_shared(sm);
    const int STAGE = 40960;

    const int m0 = (blockIdx.x + blk0) * 64;
    const int n0 = blockIdx.y * 256;
    const int t  = threadIdx.x;
    const int lane = t & 31, wid = t >> 5;
    const int wm  = (wid & 1) * 32;
    const int wn  = (wid >> 1) * 64;
    const int grp = lane >> 2, tig = lane & 3;

    // A staging: 64 rows x 8 chunks(16B); 4 thr/row, 2 chunks each
    const int arow = t >> 2, ac = (t & 3) * 2;
    const float* Ag = A + (size_t)(m0 + arow) * 1024 + ac * 8;
    // B staging: 256 rows, 1 row/thread, 8 chunks
    const __half* Wg = W + (size_t)(n0 + t) * 1024;

    const int aRow = wm + (lane & 15);
    const int aCs  = lane >> 4;
    const int bRow = wn + (lane & 7) + 8 * (lane >> 4);
    const int bCs  = (lane >> 3) & 1;

    float acc[2][8][4] = {};

    // prologue: both stages
    #pragma unroll
    for (int p = 0; p < 2; p++) {
        const int k0 = p * 64;
        const uint32_t st = smBase + p * STAGE;
        #pragma unroll
        for (int ch = 0; ch < 8; ch++)
            cpa16(st + 8192 + swB8(t, ch), Wg + k0 + ch * 8);
        cpa_commit();
        float4 x0 = *(const float4*)(Ag + k0);
        float4 y0 = *(const float4*)(Ag + k0 + 4);
        float4 x1 = *(const float4*)(Ag + k0 + 8);
        float4 y1 = *(const float4*)(Ag + k0 + 12);
        *(uint4*)(sm + p * STAGE + swB8(arow, ac))     = cvt8(x0, y0);
        *(uint4*)(sm + p * STAGE + swB8(arow, ac + 1)) = cvt8(x1, y1);
    }

    for (int it = 0; it < 16; it++) {
        const int s = it & 1;
        cpa_wait<1>();
        __syncthreads();

        // early A global loads for it+2 (hide DRAM latency under compute)
        float4 x0, y0, x1, y1;
        const bool pf = (it + 2 < 16);
        if (pf) {
            const int k0 = (it + 2) * 64;
            x0 = *(const float4*)(Ag + k0);
            y0 = *(const float4*)(Ag + k0 + 4);
            x1 = *(const float4*)(Ag + k0 + 8);
            y1 = *(const float4*)(Ag + k0 + 12);
        }

        const uint32_t bA = smBase + s * STAGE;
        const uint32_t bB = bA + 8192;
        #pragma unroll
        for (int ks = 0; ks < 4; ks++) {
            uint32_t af[2][4], bf[4][4];
            ldsm4(af[0], bA + swB8(aRow, 2 * ks + aCs));
            ldsm4(af[1], bA + swB8(aRow + 16, 2 * ks + aCs));
            #pragma unroll
            for (int nj = 0; nj < 4; nj++)
                ldsm4(bf[nj], bB + swB8(bRow + nj * 16, 2 * ks + bCs));
            #pragma unroll
            for (int mi = 0; mi < 2; mi++)
                #pragma unroll
                for (int ni = 0; ni < 8; ni++)
                    mma16816(acc[mi][ni], af[mi], &bf[ni >> 1][(ni & 1) * 2]);
        }

        __syncthreads();   // all warps done reading stage s
        if (pf) {
            const int k0 = (it + 2) * 64;
            #pragma unroll
            for (int ch = 0; ch < 8; ch++)
                cpa16(bA + 8192 + swB8(t, ch), Wg + k0 + ch * 8);
            *(uint4*)(sm + s * STAGE + swB8(arow, ac))     = cvt8(x0, y0);
            *(uint4*)(sm + s * STAGE + swB8(arow, ac + 1)) = cvt8(x1, y1);
        }
        cpa_commit();
    }

    #pragma unroll
    for (int mi = 0; mi < 2; mi++) {
        const int row = m0 + wm + mi * 16 + grp;
        #pragma unroll
        for (int ni = 0; ni < 8; ni++) {
            const int col = n0 + wn + ni * 8 + tig * 2;
            const float b0 = bias[col], b1 = bias[col + 1];
            *(__half2*)(C + (size_t)row * 512 + col) =
                __floats2half2_rn(acc[mi][ni][0] + b0, acc[mi][ni][1] + b1);
            *(__half2*)(C + (size_t)(row + 8) * 512 + col) =
                __floats2half2_rn(acc[mi][ni][2] + b0, acc[mi][ni][3] + b1);
        }
    }
}

// ---------------------------------------------------------------------------
// Q/K projection + RoPE (A fp32 in, half out)
// ---------------------------------------------------------------------------
__global__ __launch_bounds__(256)
void qk_proj(const float* __restrict__ hidden,
             const __half* __restrict__ Bq, const float* __restrict__ bq, __half* __restrict__ Cq,
             const __half* __restrict__ Bk, const float* __restrict__ bk, __half* __restrict__ Ck,
             const float* __restrict__ sp)
{
    __shared__ __align__(16) unsigned char sm[2 * 16384];
    const uint32_t smBase = (uint32_t)__cvta_generic_to_shared(sm);

    const int b = blockIdx.z >> 1, which = blockIdx.z & 1;
    const float* A = hidden + (size_t)b * ((size_t)LR * LL * LH);
    const __half* B = which ? Bk : Bq;
    const float* bias = which ? bk : bq;
    __half* C = (which ? Ck : Cq) + (size_t)b * LL * LAH;

    const int m0 = blockIdx.y * 128;
    const int n0 = blockIdx.x * 128;
    const int t  = threadIdx.x;

    const int srow = t >> 1;
    const int cb   = (t & 1) * 2;
    const float* Ag = A + (size_t)(m0 + srow) * LH + cb * 8;
    const __half* Bg = B + (size_t)(n0 + srow) * LH + cb * 8;

    const int wid  = t >> 5;
    const int wm   = (wid & 1) * 64;
    const int wn   = (wid >> 1) * 32;
    const int lane = t & 31;
    const int grp  = lane >> 2;
    const int tig  = lane & 3;

    const int aRow = wm + (lane & 15);
    const int aCs  = lane >> 4;
    const int bRow = wn + (lane & 7) + 8 * (lane >> 4);
    const int bCs  = (lane >> 3) & 1;

    float acc[4][4][4] = {};

    float4 a00, a01, a10, a11;
    uint4 b0, b1;
    a00 = *(const float4*)(Ag);      a01 = *(const float4*)(Ag + 4);
    a10 = *(const float4*)(Ag + 8);  a11 = *(const float4*)(Ag + 12);
    b0 = *(const uint4*)(Bg);        b1 = *(const uint4*)(Bg + 8);
    *(uint4*)(sm + swA(srow, cb))            = cvt8(a00, a01);
    *(uint4*)(sm + swA(srow, cb + 1))        = cvt8(a10, a11);
    *(uint4*)(sm + 8192 + swA(srow, cb))     = b0;
    *(uint4*)(sm + 8192 + swA(srow, cb + 1)) = b1;
    __syncthreads();

    const int NK = LH / 32;
    for (int it = 0; it < NK; it++) {
        const int s = it & 1;
        if (it + 1 < NK) {
            const int k0 = (it + 1) * 32;
            a00 = *(const float4*)(Ag + k0);      a01 = *(const float4*)(Ag + k0 + 4);
            a10 = *(const float4*)(Ag + k0 + 8);  a11 = *(const float4*)(Ag + k0 + 12);
            b0 = *(const uint4*)(Bg + k0);        b1 = *(const uint4*)(Bg + k0 + 8);
        }
        const uint32_t bA = smBase + s * 16384;
        const uint32_t bB = bA + 8192;
        #pragma unroll
        for (int ks = 0; ks < 2; ks++) {
            uint32_t af[4][4], bf[2][4];
            #pragma unroll
            for (int mi = 0; mi < 4; mi++)
                ldsm4(af[mi], bA + swA(aRow + mi * 16, 2 * ks + aCs));
            #pragma unroll
            for (int nj = 0; nj < 2; nj++)
                ldsm4(bf[nj], bB + swA(bRow + nj * 16, 2 * ks + bCs));
            #pragma unroll
            for (int mi = 0; mi < 4; mi++)
                #pragma unroll
                for (int ni = 0; ni < 4; ni++)
                    mma16816(acc[mi][ni], af[mi], &bf[ni >> 1][(ni & 1) * 2]);
        }
        if (it + 1 < NK) {
            unsigned char* d = sm + (s ^ 1) * 16384;
            *(uint4*)(d + swA(srow, cb))            = cvt8(a00, a01);
            *(uint4*)(d + swA(srow, cb + 1))        = cvt8(a10, a11);
            *(uint4*)(d + 8192 + swA(srow, cb))     = b0;
            *(uint4*)(d + 8192 + swA(srow, cb + 1)) = b1;
        }
        __syncthreads();
    }

    #pragma unroll
    for (int mi = 0; mi < 4; mi++) {
        const int row = m0 + wm + mi * 16 + grp;
        #pragma unroll
        for (int ni = 0; ni < 4; ni++) {
            const int col = n0 + wn + ni * 8 + tig * 2;
            const float bb0 = bias[col], bb1 = bias[col + 1];
            float c0 = acc[mi][ni][0] + bb0, c1 = acc[mi][ni][1] + bb1;
            float c2 = acc[mi][ni][2] + bb0, c3 = acc[mi][ni][3] + bb1;
            const int ii = (col & 63) >> 1;
            float sn = sp[row * 64 + ii], cs = sp[row * 64 + 32 + ii];
            float r0 = c0 * cs - c1 * sn, r1 = c1 * cs + c0 * sn;
            sn = sp[(row + 8) * 64 + ii]; cs = sp[(row + 8) * 64 + 32 + ii];
            float r2 = c2 * cs - c3 * sn, r3 = c3 * cs + c2 * sn;
            *(__half2*)(C + (size_t)row * LAH + col)       = __floats2half2_rn(r0, r1);
            *(__half2*)(C + (size_t)(row + 8) * LAH + col) = __floats2half2_rn(r2, r3);
        }
    }
}

// ---------------------------------------------------------------------------
// scores GEMM (NT): per (b,n): S = 0.125 * q @ k^T, fp32 out. K=64 single stage.
// ---------------------------------------------------------------------------
__global__ __launch_bounds__(256)
void scores_kernel(const __half* __restrict__ q, const __half* __restrict__ k,
                   float* __restrict__ s)
{
    __shared__ __align__(16) unsigned char sm[32768];
    const uint32_t smBase = (uint32_t)__cvta_generic_to_shared(sm);

    const int z = blockIdx.z;
    const int b = z >> 3, n = z & 7;
    const size_t base = (size_t)b * 512 * 512 + n * 64;

    const int m0  = blockIdx.y * 128;
    const int n0k = blockIdx.x * 128;
    const int t   = threadIdx.x;

    const int srow = t >> 1;
    const int cb   = (t & 1) * 4;
    #pragma unroll
    for (int j = 0; j < 4; j++) {
        cpa16(smBase + swB8(srow, cb + j),
              q + base + (size_t)(m0 + srow) * 512 + (cb + j) * 8);
        cpa16(smBase + 16384 + swB8(srow, cb + j),
              k + base + (size_t)(n0k + srow) * 512 + (cb + j) * 8);
    }
    cpa_commit();
    cpa_wait<0>();
    __syncthreads();

    const int wid  = t >> 5;
    const int wm   = (wid & 1) * 64;
    const int wn   = (wid >> 1) * 32;
    const int lane = t & 31;
    const int grp  = lane >> 2;
    const int tig  = lane & 3;

    const int aRow = wm + (lane & 15);
    const int aCs  = lane >> 4;
    const int bRow = wn + (lane & 7) + 8 * (lane >> 4);
    const int bCs  = (lane >> 3) & 1;

    float acc[4][4][4] = {};
    #pragma unroll
    for (int ks = 0; ks < 4; ks++) {
        uint32_t af[4][4], bf[2][4];
        #pragma unroll
        for (int mi = 0; mi < 4; mi++)
            ldsm4(af[mi], smBase + swB8(aRow + mi * 16, 2 * ks + aCs));
        #pragma unroll
        for (int nj = 0; nj < 2; nj++)
            ldsm4(bf[nj], smBase + 16384 + swB8(bRow + nj * 16, 2 * ks + bCs));
        #pragma unroll
        for (int mi = 0; mi < 4; mi++)
            #pragma unroll
            for (int ni = 0; ni < 4; ni++)
                mma16816(acc[mi][ni], af[mi], &bf[ni >> 1][(ni & 1) * 2]);
    }

    float* S = s + (size_t)z * 512 * 512;
    #pragma unroll
    for (int mi = 0; mi < 4; mi++) {
        const int row = m0 + wm + mi * 16 + grp;
        #pragma unroll
        for (int ni = 0; ni < 4; ni++) {
            const int col = n0k + wn + ni * 8 + tig * 2;
            *(float2*)(S + (size_t)row * 512 + col) =
                make_float2(acc[mi][ni][0] * 0.125f, acc[mi][ni][1] * 0.125f);
            *(float2*)(S + (size_t)(row + 8) * 512 + col) =
                make_float2(acc[mi][ni][2] * 0.125f, acc[mi][ni][3] * 0.125f);
        }
    }
}

// ---------------------------------------------------------------------------
// softmax: one warp per 512-score row -> half probs
// ---------------------------------------------------------------------------
__global__ __launch_bounds__(256)
void softmax_kernel(const float* __restrict__ s, __half* __restrict__ p)
{
    const int w    = threadIdx.x >> 5;
    const int lane = threadIdx.x & 31;
    const size_t row = (size_t)blockIdx.x * 8 + w;
    const float* src = s + row * 512;

    float4 v[4];
    float mx = -1e30f;
    #pragma unroll
    for (int j = 0; j < 4; j++) {
        v[j] = *(const float4*)(src + (lane + j * 32) * 4);
        mx = fmaxf(mx, fmaxf(fmaxf(v[j].x, v[j].y), fmaxf(v[j].z, v[j].w)));
    }
    #pragma unroll
    for (int off = 16; off; off >>= 1) mx = fmaxf(mx, __shfl_xor_sync(0xffffffffu, mx, off));

    float sum = 0.f;
    #pragma unroll
    for (int j = 0; j < 4; j++) {
        v[j].x = expf(v[j].x - mx); v[j].y = expf(v[j].y - mx);
        v[j].z = expf(v[j].z - mx); v[j].w = expf(v[j].w - mx);
        sum += v[j].x + v[j].y + v[j].z + v[j].w;
    }
    #pragma unroll
    for (int off = 16; off; off >>= 1) sum += __shfl_xor_sync(0xffffffffu, sum, off);
    const float inv = 1.f / sum;

    __half* dst = p + row * 512;
    #pragma unroll
    for (int j = 0; j < 4; j++) {
        uint2 u;
        u.x = pk2(v[j].x * inv, v[j].y * inv);
        u.y = pk2(v[j].z * inv, v[j].w * inv);
        *(uint2*)(dst + (lane + j * 32) * 4) = u;
    }
}

// ---------------------------------------------------------------------------
// ctx GEMM v3: per (b,n,r): V slice (64KB) resident; BK=64 (32 flat iters).
// A stages 3 x 16KB -> smem 112KB total, 2 CTAs/SM. BM=128 BN=64.
// ---------------------------------------------------------------------------
__global__ __launch_bounds__(256)
void h16_ctx(const __half* __restrict__ P, const __half* __restrict__ V,
             float* __restrict__ C, int z0)
{
    extern __shared__ __align__(16) unsigned char sm[];
    const uint32_t smBase = (uint32_t)__cvta_generic_to_shared(sm);
    const uint32_t aBase  = smBase + 65536;
    const int STG = 16384;

    const int z = blockIdx.x + z0;
    const int b = z >> 9, n = (z >> 6) & 7, r = z & 63;
    const int br = b * 64 + r;

    const __half* Vg = V + (size_t)br * (512 * 512) + n * 64;
    const __half* P0 = P + ((size_t)(b * 8 + n)) * (512 * 512);
    float*        Cc = C + (size_t)br * (512 * 512) + n * 64;

    const int t = threadIdx.x;

    // V preload via cp.async (group 0)
    #pragma unroll
    for (int j = 0; j < 16; j++) {
        const int i = t + 256 * j;
        const int row = i >> 3, ch = i & 7;
        cpa16(smBase + swB8(row, ch), Vg + (size_t)row * 512 + ch * 8);
    }
    cpa_commit();

    // A staging: 128 rows x 8 chunks; 2 thr/row, 4 chunks each
    const int arow = t >> 1;
    const int acb  = (t & 1) * 4;

    // prefetch flat iters 0,1: flat f -> mt = f>>3, it2 = f&7, k0 = it2*64
    #pragma unroll
    for (int p = 0; p < 2; p++) {
        const uint32_t st = aBase + p * STG;
        const __half* Am = P0 + (size_t)((p >> 3) * 128 + arow) * 512 + (p & 7) * 64 + acb * 8;
        #pragma unroll
        for (int c = 0; c < 4; c++)
            cpa16(st + swB8(arow, acb + c), Am + c * 8);
        cpa_commit();
    }

    const int wid  = t >> 5;
    const int wm   = (wid & 3) * 32;
    const int wn   = (wid >> 2) * 32;
    const int lane = t & 31;
    const int grp  = lane >> 2;
    const int tig  = lane & 3;

    const int aRow = wm + (lane & 15);
    const int aCs  = lane >> 4;
    const int bK   = (lane & 7) + 8 * ((lane >> 3) & 1);
    const int bCn  = (wn >> 3) + (lane >> 4);

    float acc[2][4][4] = {};

    for (int f = 0; f < 32; f++) {
        const int s = f - (f / 3) * 3;
        const int it2 = f & 7;
        cpa_wait<1>();
        __syncthreads();

        if (f + 2 < 32) {
            const int f2 = f + 2;
            const int s2 = f2 - (f2 / 3) * 3;
            const uint32_t st = aBase + s2 * STG;
            const __half* Am = P0 + (size_t)((f2 >> 3) * 128 + arow) * 512 + (f2 & 7) * 64 + acb * 8;
            #pragma unroll
            for (int c = 0; c < 4; c++)
                cpa16(st + swB8(arow, acb + c), Am + c * 8);
        }
        cpa_commit();

        const uint32_t bA = aBase + s * STG;
        #pragma unroll
        for (int ks = 0; ks < 4; ks++) {
            uint32_t af[2][4], bf[2][4];
            #pragma unroll
            for (int mi = 0; mi < 2; mi++)
                ldsm4(af[mi], bA + swB8(aRow + mi * 16, 2 * ks + aCs));
            #pragma unroll
            for (int nj = 0; nj < 2; nj++)
                ldsm4t(bf[nj], smBase + swB8(it2 * 64 + ks * 16 + bK, bCn + 2 * nj));
            #pragma unroll
            for (int mi = 0; mi < 2; mi++)
                #pragma unroll
                for (int ni = 0; ni < 4; ni++)
                    mma16816(acc[mi][ni], af[mi], &bf[ni >> 1][(ni & 1) * 2]);
        }

        if (it2 == 7) {
            const int mt = f >> 3;
            #pragma unroll
            for (int mi = 0; mi < 2; mi++) {
                const int row = mt * 128 + wm + mi * 16 + grp;
                #pragma unroll
                for (int ni = 0; ni < 4; ni++) {
                    const int col = wn + ni * 8 + tig * 2;
                    *(float2*)(Cc + (size_t)row * 512 + col) =
                        make_float2(acc[mi][ni][0], acc[mi][ni][1]);
                    *(float2*)(Cc + (size_t)(row + 8) * 512 + col) =
                        make_float2(acc[mi][ni][2], acc[mi][ni][3]);
                    acc[mi][ni][0] = acc[mi][ni][1] = acc[mi][ni][2] = acc[mi][ni][3] = 0.f;
                }
            }
        }
    }
}

// ---------------------------------------------------------------------------
extern "C" void kernel_launch(void* const* d_in, const int* in_sizes, int n_in,
                              void* d_out, int out_size)
{
    const float* hidden = (const float*)d_in[0];
    const float* sp     = (const float*)d_in[1];
    const float* Wq     = (const float*)d_in[2];
    const float* bq     = (const float*)d_in[3];
    const float* Wk     = (const float*)d_in[4];
    const float* bk     = (const float*)d_in[5];
    const float* Wv     = (const float*)d_in[6];
    const float* bv     = (const float*)d_in[7];
    float* out = (float*)d_out;
    (void)in_sizes; (void)n_in; (void)out_size;

    __half *wqp, *wkp, *wvp, *qp, *kp, *pp, *vp;
    float* spt;
    cudaGetSymbolAddress((void**)&wqp, g_wq);
    cudaGetSymbolAddress((void**)&wkp, g_wk);
    cudaGetSymbolAddress((void**)&wvp, g_wv);
    cudaGetSymbolAddress((void**)&qp,  g_q);
    cudaGetSymbolAddress((void**)&kp,  g_k);
    cudaGetSymbolAddress((void**)&spt, g_s);
    cudaGetSymbolAddress((void**)&pp,  g_probs);
    cudaGetSymbolAddress((void**)&vp,  g_v);

    static cudaStream_t s2 = nullptr, s3 = nullptr;
    static cudaEvent_t ev0 = nullptr, ev1 = nullptr, evA = nullptr, evB = nullptr, evC = nullptr;
    if (s2 == nullptr) {
        cudaStreamCreateWithFlags(&s2, cudaStreamNonBlocking);
        cudaStreamCreateWithFlags(&s3, cudaStreamNonBlocking);
        cudaEventCreateWithFlags(&ev0, cudaEventDisableTiming);
        cudaEventCreateWithFlags(&ev1, cudaEventDisableTiming);
        cudaEventCreateWithFlags(&evA, cudaEventDisableTiming);
        cudaEventCreateWithFlags(&evB, cudaEventDisableTiming);
        cudaEventCreateWithFlags(&evC, cudaEventDisableTiming);
        cudaFuncSetAttribute(h16_ctx, cudaFuncAttributeMaxDynamicSharedMemorySize, 114688);
        cudaFuncSetAttribute(v_proj, cudaFuncAttributeMaxDynamicSharedMemorySize, 81920);
    }

    dim3 blk(256);

    // fork at graph root
    cudaEventRecord(ev0, 0);
    cudaStreamWaitEvent(s2, ev0, 0);

    // side stream s2: Wq/Wk convert -> qk_proj -> scores -> softmax
    f2h_kernel<<<256, blk, 0, s2>>>(Wq, wqp);
    f2h_kernel<<<256, blk, 0, s2>>>(Wk, wkp);
    qk_proj<<<dim3(4, 4, 4), blk, 0, s2>>>(hidden, wqp, bq, qp, wkp, bk, kp, sp);
    scores_kernel<<<dim3(4, 4, 16), blk, 0, s2>>>(qp, kp, spt);
    softmax_kernel<<<1024, blk, 0, s2>>>(spt, pp);
    cudaEventRecord(ev1, s2);

    // main stream: Wv convert -> V projection (split by batch, BN=256 x2)
    f2h_kernel<<<256, blk>>>(Wv, wvp);
    v_proj<<<dim3(512, 2), blk, 81920>>>(hidden, wvp, bv, vp, 0);     // b=0 rows
    cudaEventRecord(evA, 0);
    v_proj<<<dim3(512, 2), blk, 81920>>>(hidden, wvp, bv, vp, 512);   // b=1 rows
    cudaEventRecord(evB, 0);

    // ctx stream s3: ctx(b0) overlaps v_proj(b1); then ctx(b1)
    cudaStreamWaitEvent(s3, evA, 0);
    cudaStreamWaitEvent(s3, ev1, 0);
    h16_ctx<<<512, blk, 114688, s3>>>(pp, vp, out, 0);
    cudaStreamWaitEvent(s3, evB, 0);
    h16_ctx<<<512, blk, 114688, s3>>>(pp, vp, out, 512);
    cudaEventRecord(evC, s3);

    // join back to origin stream for capture
    cudaStreamWaitEvent(0, evC, 0);
}

// round 13
// speedup vs baseline: 1.4039x; 1.4039x over previous
#include <cuda_runtime.h>
#include <cuda_fp16.h>
#include <cstdint>

#define LB 2
#define LR 64
#define LL 512
#define LH 1024
#define LAH 512

__device__ __half g_wq[LAH * LH], g_wk[LAH * LH], g_wv[LAH * LH];
__device__ __half g_q[(size_t)LB * LL * LAH];
__device__ __half g_k[(size_t)LB * LL * LAH];
__device__ float  g_s[(size_t)LB * 8 * LL * LL];
__device__ __half g_probs[(size_t)LB * 8 * LL * LL];
__device__ __half g_v[(size_t)LB * LR * LL * LAH];

// ---------------------------------------------------------------------------
__device__ __forceinline__ void ldsm4(uint32_t r[4], uint32_t a) {
    asm volatile("ldmatrix.sync.aligned.m8n8.x4.shared.b16 {%0,%1,%2,%3}, [%4];"
                 : "=r"(r[0]), "=r"(r[1]), "=r"(r[2]), "=r"(r[3]) : "r"(a));
}
__device__ __forceinline__ void ldsm4t(uint32_t r[4], uint32_t a) {
    asm volatile("ldmatrix.sync.aligned.m8n8.x4.trans.shared.b16 {%0,%1,%2,%3}, [%4];"
                 : "=r"(r[0]), "=r"(r[1]), "=r"(r[2]), "=r"(r[3]) : "r"(a));
}
__device__ __forceinline__ void mma16816(float c[4], const uint32_t a[4], const uint32_t b[2]) {
    asm volatile(
        "mma.sync.aligned.m16n8k16.row.col.f32.f16.f16.f32 "
        "{%0,%1,%2,%3}, {%4,%5,%6,%7}, {%8,%9}, {%0,%1,%2,%3};"
        : "+f"(c[0]), "+f"(c[1]), "+f"(c[2]), "+f"(c[3])
        : "r"(a[0]), "r"(a[1]), "r"(a[2]), "r"(a[3]), "r"(b[0]), "r"(b[1]));
}
__device__ __forceinline__ uint32_t pk2(float x, float y) {
    __half2 h = __floats2half2_rn(x, y);
    return *(uint32_t*)&h;
}
__device__ __forceinline__ uint4 cvt8(float4 a, float4 b) {
    uint4 u;
    u.x = pk2(a.x, a.y); u.y = pk2(a.z, a.w);
    u.z = pk2(b.x, b.y); u.w = pk2(b.z, b.w);
    return u;
}
// [rows][32-half] rows of 4x16B chunks, swizzle c ^ ((row>>1)&3)
__device__ __forceinline__ uint32_t swA(int row, int c) {
    return (uint32_t)((row * 4 + (c ^ ((row >> 1) & 3))) * 16);
}
// [rows][64-half] rows of 8x16B chunks (128B rows), SW128: c ^ (row&7)
__device__ __forceinline__ uint32_t swB8(int row, int c) {
    return (uint32_t)((row * 8 + (c ^ (row & 7))) * 16);
}
__device__ __forceinline__ void cpa16(uint32_t dst, const void* src) {
    asm volatile("cp.async.cg.shared.global [%0], [%1], 16;" :: "r"(dst), "l"(src));
}
__device__ __forceinline__ void cpa_commit() {
    asm volatile("cp.async.commit_group;" ::: "memory");
}
template<int N>
__device__ __forceinline__ void cpa_wait() {
    asm volatile("cp.async.wait_group %0;" :: "n"(N) : "memory");
}

// ---------------------------------------------------------------------------
// weights fp32 -> half (3 arrays in one launch): grid (256, 3)
// ---------------------------------------------------------------------------
__global__ void f2h3_kernel(const float* __restrict__ a, const float* __restrict__ b,
                            const float* __restrict__ c,
                            __half* __restrict__ da, __half* __restrict__ db,
                            __half* __restrict__ dc)
{
    const float* s; __half* d;
    if (blockIdx.y == 0)      { s = a; d = da; }
    else if (blockIdx.y == 1) { s = b; d = db; }
    else                      { s = c; d = dc; }
    const long j = ((long)blockIdx.x * 256 + threadIdx.x) * 8;
    float4 x = *(const float4*)(s + j);
    float4 y = *(const float4*)(s + j + 4);
    *(uint4*)(d + j) = cvt8(x, y);
}

// ---------------------------------------------------------------------------
// V projection: C = hidden @ Wv^T + bv (half out)
// M=65536 N=512 K=1024. BM=64, BN=512, BK=64. 8 warps, warp 32x128.
// 3-stage pipeline: B via cp.async, A via register staging (fp32->half).
// stage = A 8KB + B 64KB = 72KB; 3 stages = 216KB dynamic smem.
// ---------------------------------------------------------------------------
__global__ __launch_bounds__(256, 1)
void v_proj(const float* __restrict__ A, const __half* __restrict__ W,
            const float* __restrict__ bias, __half* __restrict__ C)
{
    extern __shared__ __align__(16) unsigned char sm[];
    const uint32_t smBase = (uint32_t)__cvta_generic_to_shared(sm);
    const int STAGE = 73728;

    const int m0 = blockIdx.x * 64;
    const int t  = threadIdx.x;
    const int lane = t & 31, wid = t >> 5;
    const int wm  = (wid & 1) * 32;
    const int wn  = (wid >> 1) * 128;
    const int grp = lane >> 2, tig = lane & 3;

    // A staging: 64 rows x 64 fp32 -> half; 4 threads/row, 2 chunks each
    const int arow = t >> 2, ac = t & 3;
    const float* Ag = A + (size_t)(m0 + arow) * 1024 + ac * 16;

    const int aRow = wm + (lane & 15);
    const int aCs  = lane >> 4;
    const int bRow = wn + (lane & 7) + 8 * (lane >> 4);
    const int bCs  = (lane >> 3) & 1;

    float acc[2][16][4] = {};

    // prologue: stages 0,1
    #pragma unroll
    for (int p = 0; p < 2; p++) {
        const int k0 = p * 64;
        const uint32_t st = smBase + p * STAGE;
        #pragma unroll
        for (int j = 0; j < 16; j++) {
            const int i = t + 256 * j;
            const int row = i >> 3, ch = i & 7;
            cpa16(st + 8192 + swB8(row, ch), W + (size_t)row * 1024 + k0 + ch * 8);
        }
        float4 x0 = *(const float4*)(Ag + k0);
        float4 y0 = *(const float4*)(Ag + k0 + 4);
        float4 x1 = *(const float4*)(Ag + k0 + 8);
        float4 y1 = *(const float4*)(Ag + k0 + 12);
        *(uint4*)(sm + p * STAGE + swB8(arow, 2 * ac))     = cvt8(x0, y0);
        *(uint4*)(sm + p * STAGE + swB8(arow, 2 * ac + 1)) = cvt8(x1, y1);
        cpa_commit();
    }

    for (int it = 0; it < 16; it++) {
        const int s = it - (it / 3) * 3;
        cpa_wait<1>();
        __syncthreads();

        // prefetch stage it+2
        float4 px0, py0, px1, py1;
        const bool pf = (it + 2 < 16);
        const int s2 = (it + 2) - ((it + 2) / 3) * 3;
        if (pf) {
            const int k0 = (it + 2) * 64;
            const uint32_t st = smBase + s2 * STAGE;
            #pragma unroll
            for (int j = 0; j < 16; j++) {
                const int i = t + 256 * j;
                const int row = i >> 3, ch = i & 7;
                cpa16(st + 8192 + swB8(row, ch), W + (size_t)row * 1024 + k0 + ch * 8);
            }
            px0 = *(const float4*)(Ag + k0);
            py0 = *(const float4*)(Ag + k0 + 4);
            px1 = *(const float4*)(Ag + k0 + 8);
            py1 = *(const float4*)(Ag + k0 + 12);
        }

        const uint32_t bA = smBase + s * STAGE;
        const uint32_t bB = bA + 8192;
        #pragma unroll
        for (int ks = 0; ks < 4; ks++) {
            uint32_t af[2][4];
            ldsm4(af[0], bA + swB8(aRow, 2 * ks + aCs));
            ldsm4(af[1], bA + swB8(aRow + 16, 2 * ks + aCs));
            #pragma unroll
            for (int nj = 0; nj < 8; nj++) {
                uint32_t bf[4];
                ldsm4(bf, bB + swB8(bRow + nj * 16, 2 * ks + bCs));
                mma16816(acc[0][2 * nj],     af[0], &bf[0]);
                mma16816(acc[0][2 * nj + 1], af[0], &bf[2]);
                mma16816(acc[1][2 * nj],     af[1], &bf[0]);
                mma16816(acc[1][2 * nj + 1], af[1], &bf[2]);
            }
        }

        if (pf) {
            unsigned char* d = sm + s2 * STAGE;
            *(uint4*)(d + swB8(arow, 2 * ac))     = cvt8(px0, py0);
            *(uint4*)(d + swB8(arow, 2 * ac + 1)) = cvt8(px1, py1);
        }
        cpa_commit();
    }

    #pragma unroll
    for (int mi = 0; mi < 2; mi++) {
        const int row = m0 + wm + mi * 16 + grp;
        #pragma unroll
        for (int ni = 0; ni < 16; ni++) {
            const int col = wn + ni * 8 + tig * 2;
            const float b0 = bias[col], b1 = bias[col + 1];
            *(__half2*)(C + (size_t)row * 512 + col) =
                __floats2half2_rn(acc[mi][ni][0] + b0, acc[mi][ni][1] + b1);
            *(__half2*)(C + (size_t)(row + 8) * 512 + col) =
                __floats2half2_rn(acc[mi][ni][2] + b0, acc[mi][ni][3] + b1);
        }
    }
}

// ---------------------------------------------------------------------------
// Q/K projection + RoPE (A fp32 in, half out)
// ---------------------------------------------------------------------------
__global__ __launch_bounds__(256)
void qk_proj(const float* __restrict__ hidden,
             const __half* __restrict__ Bq, const float* __restrict__ bq, __half* __restrict__ Cq,
             const __half* __restrict__ Bk, const float* __restrict__ bk, __half* __restrict__ Ck,
             const float* __restrict__ sp)
{
    __shared__ __align__(16) unsigned char sm[2 * 16384];
    const uint32_t smBase = (uint32_t)__cvta_generic_to_shared(sm);

    const int b = blockIdx.z >> 1, which = blockIdx.z & 1;
    const float* A = hidden + (size_t)b * ((size_t)LR * LL * LH);
    const __half* B = which ? Bk : Bq;
    const float* bias = which ? bk : bq;
    __half* C = (which ? Ck : Cq) + (size_t)b * LL * LAH;

    const int m0 = blockIdx.y * 128;
    const int n0 = blockIdx.x * 128;
    const int t  = threadIdx.x;

    const int srow = t >> 1;
    const int cb   = (t & 1) * 2;
    const float* Ag = A + (size_t)(m0 + srow) * LH + cb * 8;
    const __half* Bg = B + (size_t)(n0 + srow) * LH + cb * 8;

    const int wid  = t >> 5;
    const int wm   = (wid & 1) * 64;
    const int wn   = (wid >> 1) * 32;
    const int lane = t & 31;
    const int grp  = lane >> 2;
    const int tig  = lane & 3;

    const int aRow = wm + (lane & 15);
    const int aCs  = lane >> 4;
    const int bRow = wn + (lane & 7) + 8 * (lane >> 4);
    const int bCs  = (lane >> 3) & 1;

    float acc[4][4][4] = {};

    float4 a00, a01, a10, a11;
    uint4 b0, b1;
    a00 = *(const float4*)(Ag);      a01 = *(const float4*)(Ag + 4);
    a10 = *(const float4*)(Ag + 8);  a11 = *(const float4*)(Ag + 12);
    b0 = *(const uint4*)(Bg);        b1 = *(const uint4*)(Bg + 8);
    *(uint4*)(sm + swA(srow, cb))            = cvt8(a00, a01);
    *(uint4*)(sm + swA(srow, cb + 1))        = cvt8(a10, a11);
    *(uint4*)(sm + 8192 + swA(srow, cb))     = b0;
    *(uint4*)(sm + 8192 + swA(srow, cb + 1)) = b1;
    __syncthreads();

    const int NK = LH / 32;
    for (int it = 0; it < NK; it++) {
        const int s = it & 1;
        if (it + 1 < NK) {
            const int k0 = (it + 1) * 32;
            a00 = *(const float4*)(Ag + k0);      a01 = *(const float4*)(Ag + k0 + 4);
            a10 = *(const float4*)(Ag + k0 + 8);  a11 = *(const float4*)(Ag + k0 + 12);
            b0 = *(const uint4*)(Bg + k0);        b1 = *(const uint4*)(Bg + k0 + 8);
        }
        const uint32_t bA = smBase + s * 16384;
        const uint32_t bB = bA + 8192;
        #pragma unroll
        for (int ks = 0; ks < 2; ks++) {
            uint32_t af[4][4], bf[2][4];
            #pragma unroll
            for (int mi = 0; mi < 4; mi++)
                ldsm4(af[mi], bA + swA(aRow + mi * 16, 2 * ks + aCs));
            #pragma unroll
            for (int nj = 0; nj < 2; nj++)
                ldsm4(bf[nj], bB + swA(bRow + nj * 16, 2 * ks + bCs));
            #pragma unroll
            for (int mi = 0; mi < 4; mi++)
                #pragma unroll
                for (int ni = 0; ni < 4; ni++)
                    mma16816(acc[mi][ni], af[mi], &bf[ni >> 1][(ni & 1) * 2]);
        }
        if (it + 1 < NK) {
            unsigned char* d = sm + (s ^ 1) * 16384;
            *(uint4*)(d + swA(srow, cb))            = cvt8(a00, a01);
            *(uint4*)(d + swA(srow, cb + 1))        = cvt8(a10, a11);
            *(uint4*)(d + 8192 + swA(srow, cb))     = b0;
            *(uint4*)(d + 8192 + swA(srow, cb + 1)) = b1;
        }
        __syncthreads();
    }

    #pragma unroll
    for (int mi = 0; mi < 4; mi++) {
        const int row = m0 + wm + mi * 16 + grp;
        #pragma unroll
        for (int ni = 0; ni < 4; ni++) {
            const int col = n0 + wn + ni * 8 + tig * 2;
            const float bb0 = bias[col], bb1 = bias[col + 1];
            float c0 = acc[mi][ni][0] + bb0, c1 = acc[mi][ni][1] + bb1;
            float c2 = acc[mi][ni][2] + bb0, c3 = acc[mi][ni][3] + bb1;
            const int ii = (col & 63) >> 1;
            float sn = sp[row * 64 + ii], cs = sp[row * 64 + 32 + ii];
            float r0 = c0 * cs - c1 * sn, r1 = c1 * cs + c0 * sn;
            sn = sp[(row + 8) * 64 + ii]; cs = sp[(row + 8) * 64 + 32 + ii];
            float r2 = c2 * cs - c3 * sn, r3 = c3 * cs + c2 * sn;
            *(__half2*)(C + (size_t)row * LAH + col)       = __floats2half2_rn(r0, r1);
            *(__half2*)(C + (size_t)(row + 8) * LAH + col) = __floats2half2_rn(r2, r3);
        }
    }
}

// ---------------------------------------------------------------------------
// scores GEMM (NT): per (b,n): S = 0.125 * q @ k^T, fp32 out. K=64 single stage.
// ---------------------------------------------------------------------------
__global__ __launch_bounds__(256)
void scores_kernel(const __half* __restrict__ q, const __half* __restrict__ k,
                   float* __restrict__ s)
{
    __shared__ __align__(16) unsigned char sm[32768];
    const uint32_t smBase = (uint32_t)__cvta_generic_to_shared(sm);

    const int z = blockIdx.z;
    const int b = z >> 3, n = z & 7;
    const size_t base = (size_t)b * 512 * 512 + n * 64;

    const int m0  = blockIdx.y * 128;
    const int n0k = blockIdx.x * 128;
    const int t   = threadIdx.x;

    const int srow = t >> 1;
    const int cb   = (t & 1) * 4;
    #pragma unroll
    for (int j = 0; j < 4; j++) {
        cpa16(smBase + swB8(srow, cb + j),
              q + base + (size_t)(m0 + srow) * 512 + (cb + j) * 8);
        cpa16(smBase + 16384 + swB8(srow, cb + j),
              k + base + (size_t)(n0k + srow) * 512 + (cb + j) * 8);
    }
    cpa_commit();
    cpa_wait<0>();
    __syncthreads();

    const int wid  = t >> 5;
    const int wm   = (wid & 1) * 64;
    const int wn   = (wid >> 1) * 32;
    const int lane = t & 31;
    const int grp  = lane >> 2;
    const int tig  = lane & 3;

    const int aRow = wm + (lane & 15);
    const int aCs  = lane >> 4;
    const int bRow = wn + (lane & 7) + 8 * (lane >> 4);
    const int bCs  = (lane >> 3) & 1;

    float acc[4][4][4] = {};
    #pragma unroll
    for (int ks = 0; ks < 4; ks++) {
        uint32_t af[4][4], bf[2][4];
        #pragma unroll
        for (int mi = 0; mi < 4; mi++)
            ldsm4(af[mi], smBase + swB8(aRow + mi * 16, 2 * ks + aCs));
        #pragma unroll
        for (int nj = 0; nj < 2; nj++)
            ldsm4(bf[nj], smBase + 16384 + swB8(bRow + nj * 16, 2 * ks + bCs));
        #pragma unroll
        for (int mi = 0; mi < 4; mi++)
            #pragma unroll
            for (int ni = 0; ni < 4; ni++)
                mma16816(acc[mi][ni], af[mi], &bf[ni >> 1][(ni & 1) * 2]);
    }

    float* S = s + (size_t)z * 512 * 512;
    #pragma unroll
    for (int mi = 0; mi < 4; mi++) {
        const int row = m0 + wm + mi * 16 + grp;
        #pragma unroll
        for (int ni = 0; ni < 4; ni++) {
            const int col = n0k + wn + ni * 8 + tig * 2;
            *(float2*)(S + (size_t)row * 512 + col) =
                make_float2(acc[mi][ni][0] * 0.125f, acc[mi][ni][1] * 0.125f);
            *(float2*)(S + (size_t)(row + 8) * 512 + col) =
                make_float2(acc[mi][ni][2] * 0.125f, acc[mi][ni][3] * 0.125f);
        }
    }
}

// ---------------------------------------------------------------------------
// softmax: one warp per 512-score row -> half probs
// ---------------------------------------------------------------------------
__global__ __launch_bounds__(256)
void softmax_kernel(const float* __restrict__ s, __half* __restrict__ p)
{
    const int w    = threadIdx.x >> 5;
    const int lane = threadIdx.x & 31;
    const size_t row = (size_t)blockIdx.x * 8 + w;
    const float* src = s + row * 512;

    float4 v[4];
    float mx = -1e30f;
    #pragma unroll
    for (int j = 0; j < 4; j++) {
        v[j] = *(const float4*)(src + (lane + j * 32) * 4);
        mx = fmaxf(mx, fmaxf(fmaxf(v[j].x, v[j].y), fmaxf(v[j].z, v[j].w)));
    }
    #pragma unroll
    for (int off = 16; off; off >>= 1) mx = fmaxf(mx, __shfl_xor_sync(0xffffffffu, mx, off));

    float sum = 0.f;
    #pragma unroll
    for (int j = 0; j < 4; j++) {
        v[j].x = expf(v[j].x - mx); v[j].y = expf(v[j].y - mx);
        v[j].z = expf(v[j].z - mx); v[j].w = expf(v[j].w - mx);
        sum += v[j].x + v[j].y + v[j].z + v[j].w;
    }
    #pragma unroll
    for (int off = 16; off; off >>= 1) sum += __shfl_xor_sync(0xffffffffu, sum, off);
    const float inv = 1.f / sum;

    __half* dst = p + row * 512;
    #pragma unroll
    for (int j = 0; j < 4; j++) {
        uint2 u;
        u.x = pk2(v[j].x * inv, v[j].y * inv);
        u.y = pk2(v[j].z * inv, v[j].w * inv);
        *(uint2*)(dst + (lane + j * 32) * 4) = u;
    }
}

// ---------------------------------------------------------------------------
// ctx GEMM: per (b,n,r): V head-slice (512x64 half = 64KB) resident in smem,
// flattened 64-iter cp.async pipeline over (mt, it). BM=128 BN=64 BK=32.
// smem: V 64KB + 3 x 8KB A stages = 88KB (2 CTAs/SM).
// ---------------------------------------------------------------------------
__global__ __launch_bounds__(256)
void h16_ctx(const __half* __restrict__ P, const __half* __restrict__ V,
             float* __restrict__ C)
{
    extern __shared__ __align__(16) unsigned char sm[];
    const uint32_t smBase = (uint32_t)__cvta_generic_to_shared(sm);

    const int z = blockIdx.x;
    const int b = z >> 9, n = (z >> 6) & 7, r = z & 63;
    const int br = b * 64 + r;

    const __half* Vg = V + (size_t)br * (512 * 512) + n * 64;
    const __half* P0 = P + ((size_t)(b * 8 + n)) * (512 * 512);
    float*        Cc = C + (size_t)br * (512 * 512) + n * 64;

    const int t = threadIdx.x;

    // V preload via cp.async (group 0)
    #pragma unroll
    for (int j = 0; j < 16; j++) {
        const int i = t + 256 * j;
        const int row = i >> 3, ch = i & 7;
        cpa16(smBase + swB8(row, ch), Vg + (size_t)row * 512 + ch * 8);
    }
    cpa_commit();

    const int arow = t >> 1;
    const int acb  = (t & 1) * 2;

    #pragma unroll
    for (int p = 0; p < 2; p++) {
        const uint32_t st = smBase + 65536 + p * 8192;
        const __half* Am = P0 + (size_t)((p >> 4) * 128 + arow) * 512 + (p & 15) * 32 + acb * 8;
        cpa16(st + swA(arow, acb), Am);
        cpa16(st + swA(arow, acb + 1), Am + 8);
        cpa_commit();
    }

    const int wid  = t >> 5;
    const int wm   = (wid & 3) * 32;
    const int wn   = (wid >> 2) * 32;
    const int lane = t & 31;
    const int grp  = lane >> 2;
    const int tig  = lane & 3;

    const int aRow = wm + (lane & 15);
    const int aCs  = lane >> 4;
    const int bK   = (lane & 7) + 8 * ((lane >> 3) & 1);
    const int bCn  = (wn >> 3) + (lane >> 4);

    float acc[2][4][4] = {};

    for (int f = 0; f < 64; f++) {
        const int s = f - (f / 3) * 3;
        const int it = f & 15;
        cpa_wait<1>();
        __syncthreads();

        if (f + 2 < 64) {
            const int f2 = f + 2;
            const int s2 = f2 - (f2 / 3) * 3;
            const uint32_t st = smBase + 65536 + s2 * 8192;
            const __half* Am = P0 + (size_t)((f2 >> 4) * 128 + arow) * 512 + (f2 & 15) * 32 + acb * 8;
            cpa16(st + swA(arow, acb), Am);
            cpa16(st + swA(arow, acb + 1), Am + 8);
        }
        cpa_commit();

        const uint32_t bA = smBase + 65536 + s * 8192;
        #pragma unroll
        for (int ks = 0; ks < 2; ks++) {
            uint32_t af[2][4], bf[2][4];
            #pragma unroll
            for (int mi = 0; mi < 2; mi++)
                ldsm4(af[mi], bA + swA(aRow + mi * 16, 2 * ks + aCs));
            #pragma unroll
            for (int nj = 0; nj < 2; nj++)
                ldsm4t(bf[nj], smBase + swB8(it * 32 + ks * 16 + bK, bCn + 2 * nj));
            #pragma unroll
            for (int mi = 0; mi < 2; mi++)
                #pragma unroll
                for (int ni = 0; ni < 4; ni++)
                    mma16816(acc[mi][ni], af[mi], &bf[ni >> 1][(ni & 1) * 2]);
        }

        if (it == 15) {
            const int mt = f >> 4;
            #pragma unroll
            for (int mi = 0; mi < 2; mi++) {
                const int row = mt * 128 + wm + mi * 16 + grp;
                #pragma unroll
                for (int ni = 0; ni < 4; ni++) {
                    const int col = wn + ni * 8 + tig * 2;
                    *(float2*)(Cc + (size_t)row * 512 + col) =
                        make_float2(acc[mi][ni][0], acc[mi][ni][1]);
                    *(float2*)(Cc + (size_t)(row + 8) * 512 + col) =
                        make_float2(acc[mi][ni][2], acc[mi][ni][3]);
                    acc[mi][ni][0] = acc[mi][ni][1] = acc[mi][ni][2] = acc[mi][ni][3] = 0.f;
                }
            }
        }
    }
}

// ---------------------------------------------------------------------------
extern "C" void kernel_launch(void* const* d_in, const int* in_sizes, int n_in,
                              void* d_out, int out_size)
{
    const float* hidden = (const float*)d_in[0];
    const float* sp     = (const float*)d_in[1];
    const float* Wq     = (const float*)d_in[2];
    const float* bq     = (const float*)d_in[3];
    const float* Wk     = (const float*)d_in[4];
    const float* bk     = (const float*)d_in[5];
    const float* Wv     = (const float*)d_in[6];
    const float* bv     = (const float*)d_in[7];
    float* out = (float*)d_out;
    (void)in_sizes; (void)n_in; (void)out_size;

    __half *wqp, *wkp, *wvp, *qp, *kp, *pp, *vp;
    float* spt;
    cudaGetSymbolAddress((void**)&wqp, g_wq);
    cudaGetSymbolAddress((void**)&wkp, g_wk);
    cudaGetSymbolAddress((void**)&wvp, g_wv);
    cudaGetSymbolAddress((void**)&qp,  g_q);
    cudaGetSymbolAddress((void**)&kp,  g_k);
    cudaGetSymbolAddress((void**)&spt, g_s);
    cudaGetSymbolAddress((void**)&pp,  g_probs);
    cudaGetSymbolAddress((void**)&vp,  g_v);

    static cudaStream_t s2 = nullptr;
    static cudaEvent_t ev0 = nullptr, ev1 = nullptr;
    if (s2 == nullptr) {
        cudaStreamCreateWithFlags(&s2, cudaStreamNonBlocking);
        cudaEventCreateWithFlags(&ev0, cudaEventDisableTiming);
        cudaEventCreateWithFlags(&ev1, cudaEventDisableTiming);
        cudaFuncSetAttribute(h16_ctx, cudaFuncAttributeMaxDynamicSharedMemorySize, 90112);
        cudaFuncSetAttribute(v_proj, cudaFuncAttributeMaxDynamicSharedMemorySize, 221184);
    }

    dim3 blk(256);

    // weights fp32 -> half (stream 0)
    f2h3_kernel<<<dim3(256, 3), blk>>>(Wq, Wk, Wv, wqp, wkp, wvp);

    // fork: qk/scores/softmax chain on side stream, overlapped with v_proj
    cudaEventRecord(ev0, 0);
    cudaStreamWaitEvent(s2, ev0, 0);
    qk_proj<<<dim3(4, 4, 4), blk, 0, s2>>>(hidden, wqp, bq, qp, wkp, bk, kp, sp);
    scores_kernel<<<dim3(4, 4, 16), blk, 0, s2>>>(qp, kp, spt);
    softmax_kernel<<<1024, blk, 0, s2>>>(spt, pp);
    cudaEventRecord(ev1, s2);

    // V projection on stream 0 (BK=64, 3-stage cp.async)
    v_proj<<<dim3(1024), blk, 221184>>>(hidden, wvp, bv, vp);

    // join, then ctx
    cudaStreamWaitEvent(0, ev1, 0);
    h16_ctx<<<1024, blk, 90112>>>(pp, vp, out);
}